// round 8
// baseline (speedup 1.0000x reference)
#include <cuda_runtime.h>
#include <cstdint>

#define BS 2
#define NF 16
#define C  32
#define H  128
#define W  128
#define HW (H*W)
#define NM 8
#define NK 3
#define MID (NF/2)

#define PCHUNK 64            // pixels per block
#define PNCH (HW/PCHUNK)     // 256 chunks
#define CG 4                 // channel groups (8 channels = 8 warps each)

typedef unsigned long long ull;

// partials: [b][c][m][ch]  rows of PNCH=256 floats (512 KB total)
__device__ float g_part[BS*C*NM*PNCH];
__device__ float g_pooled[BS*NM*C];
__device__ int   g_ctr;          // zero-init; self-resets each launch

// ---------------------------------------------------------------------------
// Fused masks+pool. grid (PNCH, CG, BS) = 2048 blocks, 256 thr = 8 warps.
//   P2a: mask partials straight from gmem (mid-frame, L2-hot), 4-way c-split
//   P2b: combine partials -> smask; cg==0 writes tile to gmem output
//   P3 : pool 16 frames; warp owns channel cg*8+wid; lane owns px pair
//   P4 : warp butterfly reduce -> g_part
// ---------------------------------------------------------------------------
__global__ void __launch_bounds__(256, 4)
fused_kernel(const float* __restrict__ dec,
             const float* __restrict__ seg_w,
             const float* __restrict__ seg_b,
             float* __restrict__ masks_out)
{
    __shared__ float part[4][NM][PCHUNK];   // 8 KB
    __shared__ float smask[NM*PCHUNK];      // 2 KB
    __shared__ float sw[NM*C];              // 1 KB

    const int tid  = threadIdx.x;
    const int ch   = blockIdx.x;
    const int cg   = blockIdx.y;
    const int b    = blockIdx.z;
    const int wid  = tid >> 5;
    const int lane = tid & 31;

    if (tid < NM*C) sw[tid] = seg_w[tid];
    __syncthreads();

    // ---- P2a: mask partials. thread = (px, qc); 8 coalesced gmem loads ----
    {
        const int px = tid & 63;
        const int qc = tid >> 6;            // 0..3 -> channels qc*8..qc*8+7
        const float* src = dec + ((size_t)(b*NF + MID)*C + qc*8)*HW
                               + (size_t)ch*PCHUNK + px;
        float v[8];
#pragma unroll
        for (int i = 0; i < 8; i++) v[i] = src[(size_t)i*HW];

        float pm[NM];
#pragma unroll
        for (int m = 0; m < NM; m++) pm[m] = 0.f;
#pragma unroll
        for (int i = 0; i < 8; i++)
#pragma unroll
            for (int m = 0; m < NM; m++)
                pm[m] += v[i] * sw[m*C + qc*8 + i];
#pragma unroll
        for (int m = 0; m < NM; m++) part[qc][m][px] = pm[m];
    }
    __syncthreads();

    // ---- P2b: combine (512 outputs / 256 thr = 2 each) ----
#pragma unroll
    for (int r = 0; r < 2; r++) {
        int k  = tid + r*256;
        int m  = k >> 6;
        int px = k & 63;
        float a = part[0][m][px] + part[1][m][px]
                + part[2][m][px] + part[3][m][px] + seg_b[m];
        smask[m*PCHUNK + px] = a;
        if (cg == 0)
            masks_out[((size_t)b*NM + m)*HW + (size_t)ch*PCHUNK + px] = a;
    }
    __syncthreads();

    // ---- P3: pooling ----
    const int c = cg*8 + wid;

    ull mk[NM];
#pragma unroll
    for (int m = 0; m < NM; m++)
        mk[m] = reinterpret_cast<const ull*>(smask + m*PCHUNK)[lane];

    ull acc[NM];
#pragma unroll
    for (int m = 0; m < NM; m++) acc[m] = 0ULL;

    const float* base = dec + ((size_t)b*NF*C + c)*HW + (size_t)ch*PCHUNK;

#pragma unroll 4
    for (int f = 0; f < NF; f++) {
        ull v = reinterpret_cast<const ull*>(base + (size_t)f*C*HW)[lane];
#pragma unroll
        for (int m = 0; m < NM; m++)
            asm("fma.rn.f32x2 %0, %1, %2, %0;" : "+l"(acc[m]) : "l"(v), "l"(mk[m]));
    }

    // ---- P4: reduce ----
#pragma unroll
    for (int m = 0; m < NM; m++) {
        float2 a = *reinterpret_cast<float2*>(&acc[m]);
        float s = a.x + a.y;
#pragma unroll
        for (int off = 16; off; off >>= 1)
            s += __shfl_xor_sync(0xffffffffu, s, off);
        if (lane == 0)
            g_part[(((size_t)b*C + c)*NM + m)*PNCH + ch] = s;
    }
}

// ---------------------------------------------------------------------------
// Reduce + logits: 64 blocks × 256 thr. Warp w reduces row blockIdx.x*8+w
// (256 floats, two float4 loads per lane). LAST block computes the logits.
// ---------------------------------------------------------------------------
__global__ void __launch_bounds__(256)
reduce_logits_kernel(const float* __restrict__ lw,
                     const float* __restrict__ lb,
                     float* __restrict__ out)
{
    const int tid  = threadIdx.x;
    const int wid  = tid >> 5;
    const int lane = tid & 31;
    const int row  = blockIdx.x*8 + wid;    // (b*C + c)*NM + m, 512 rows

    const float4* src = reinterpret_cast<const float4*>(g_part + (size_t)row*PNCH);
    float4 a = src[lane];
    float4 d = src[lane + 32];
    float s = (a.x+a.y+a.z+a.w) + (d.x+d.y+d.z+d.w);
#pragma unroll
    for (int off = 16; off; off >>= 1)
        s += __shfl_xor_sync(0xffffffffu, s, off);

    if (lane == 0) {
        int m = row & (NM-1);
        int c = (row / NM) & (C-1);
        int b = row / (NM*C);
        g_pooled[((size_t)b*NM + m)*C + c] = s * (1.0f / NF);
    }

    __shared__ bool is_last;
    __syncthreads();
    if (tid == 0) {
        __threadfence();
        is_last = (atomicAdd(&g_ctr, 1) == gridDim.x - 1);
    }
    __syncthreads();

    if (is_last) {
        __threadfence();                   // acquire pooled writes
        if (tid < BS*NM*NK) {
            int k  = tid % NK;
            int bm = tid / NK;
            const float* p = g_pooled + (size_t)bm*C;
            float acc = lb[k];
#pragma unroll
            for (int c = 0; c < C; c++) acc += p[c] * lw[k*C + c];
            out[tid] = acc;
        }
        if (tid == 0) g_ctr = 0;           // reset for next graph replay
    }
}

// ---------------------------------------------------------------------------
extern "C" void kernel_launch(void* const* d_in, const int* in_sizes, int n_in,
                              void* d_out, int out_size)
{
    const float* dec   = (const float*)d_in[0];
    const float* seg_w = (const float*)d_in[1];
    const float* seg_b = (const float*)d_in[2];
    const float* lw    = (const float*)d_in[3];
    const float* lb    = (const float*)d_in[4];

    float* out    = (float*)d_out;
    float* logits = out;                 // 48 floats
    float* masks  = out + BS*NM*NK;      // 262144 floats

    fused_kernel        <<<dim3(PNCH, CG, BS), 256>>>(dec, seg_w, seg_b, masks);
    reduce_logits_kernel<<<BS*C*NM/8, 256>>>(lw, lb, logits);
}